// round 13
// baseline (speedup 1.0000x reference)
#include <cuda_runtime.h>

#define BATCH 512
#define SEQ   200
#define TT    10
#define EMB   25
#define EMB_P 28           // padded x row in smem
#define HH    64
#define G3    192          // 3*H
#define BT    7            // batch rows per GRU block
#define BLK_PER_DIR 74     // ceil(512/7)

typedef unsigned long long u64;

// ---------------- scratch (static device memory; no allocation) ----------------
__device__ float g_x  [SEQ * BATCH * EMB];  // [s][b][25] pooled embeddings (10MB, L2-resident)
__device__ float g_hsf[SEQ * BATCH * HH];   // [s][b][64]
__device__ float g_hsb[SEQ * BATCH * HH];   // [s][b][64] (stored at original s)
__device__ float g_hT [BATCH * HH];
__device__ float g_mask[SEQ * BATCH];       // [s][b] step mask as float
__device__ float g_sink[2];                 // dummy-kernel sink (ncu launch alignment)

// ---------------- f32x2 helpers ----------------
__device__ __forceinline__ u64 pack2(float lo, float hi) {
    u64 r;
    asm("mov.b64 %0, {%1, %2};" : "=l"(r) : "r"(__float_as_uint(lo)), "r"(__float_as_uint(hi)));
    return r;
}
__device__ __forceinline__ void unpack2(u64 v, float& lo, float& hi) {
    unsigned int a, b;
    asm("mov.b64 {%0, %1}, %2;" : "=r"(a), "=r"(b) : "l"(v));
    lo = __uint_as_float(a); hi = __uint_as_float(b);
}
__device__ __forceinline__ u64 fma2(u64 a, u64 b, u64 c) {
    u64 d;
    asm("fma.rn.f32x2 %0, %1, %2, %3;" : "=l"(d) : "l"(a), "l"(b), "l"(c));
    return d;
}
__device__ __forceinline__ u64 add2(u64 a, u64 b) {
    u64 d;
    asm("add.rn.f32x2 %0, %1, %2;" : "=l"(d) : "l"(a), "l"(b));
    return d;
}
__device__ __forceinline__ float hsum2(u64 v) {
    float lo, hi; unpack2(v, lo, hi); return lo + hi;
}
__device__ __forceinline__ u64 shfl2(u64 v, int m) {
    float lo, hi; unpack2(v, lo, hi);
    lo = __shfl_xor_sync(0xFFFFFFFFu, lo, m);
    hi = __shfl_xor_sync(0xFFFFFFFFu, hi, m);
    return pack2(lo, hi);
}

// fast activations (ex2.approx based, ~1e-6 rel err)
__device__ __forceinline__ float sigx(float x) {
    return __fdividef(1.0f, 1.0f + __expf(-x));
}
__device__ __forceinline__ float tanhx(float x) {
    return fmaf(2.0f, sigx(2.0f * x), -1.0f);
}

// ---------------- dummy kernels (shift ncu's profiled launch onto kB) ----------
__global__ void kD(int i) { if (threadIdx.x == 0) g_sink[i] = 0.0f; }

// =====================================================================
// Kernel A: embedding gather + masked mean (projection lives in kB).
// =====================================================================
__global__ __launch_bounds__(256) void kA(const int* __restrict__ inp,
                                          const float* __restrict__ emb) {
    const int tid = threadIdx.x;
    const int base = blockIdx.x * 32;

    for (int o = tid; o < 32 * EMB; o += 256) {
        int r = o / EMB, e = o - r * EMB;
        const int* ip = inp + (size_t)(base + r) * TT;
        float sum = 0.0f; int cnt = 0;
#pragma unroll
        for (int t = 0; t < TT; t++) {
            int idx = ip[t];
            if (idx != 0) { sum += emb[(size_t)idx * EMB + e]; cnt++; }
        }
        int row = base + r;
        int b = row / SEQ, s = row - b * SEQ;
        g_x[((size_t)s * BATCH + b) * EMB + e] = sum / (float)(cnt > 0 ? cnt : 1);
    }
    if (tid < 32) {
        int row = base + tid;
        int b = row / SEQ, s = row - b * SEQ;
        g_mask[s * BATCH + b] = (inp[(size_t)row * TT] != 0) ? 1.0f : 0.0f;
    }
}

// =====================================================================
// Kernel B: bidirectional GRU, fused projection, register-resident gates.
//   grid = 148 (1 block/SM), 512 threads.
//   tid = rg*256 + ct*4 + kq:
//     ct (0..63): gate index j; thread owns cols {ct, ct+64, ct+128} = z,r,h
//     kq (0..3):  k-quarter (h k = 16t+4kq chunks; x e = 6kq..6kq+5, kq3 +tail)
//     rg (0..1):  row half (rows 0-3 / 4-6)
//   k-reduction via 2-round shfl.xor over kq lanes (in-warp); gate math fully
//   in registers (h_old register-resident). ONE __syncthreads per step.
// =====================================================================
__global__ __launch_bounds__(512, 1) void kB(const float* __restrict__ Uf,
                                             const float* __restrict__ bf,
                                             const float* __restrict__ Ub,
                                             const float* __restrict__ bb,
                                             const float* __restrict__ Wf,
                                             const float* __restrict__ Wb) {
    __shared__ __align__(16) float sh[2][BT][HH];       // double-buffered h
    __shared__ __align__(16) float xb[2][BT][EMB_P];    // double-buffered x

    const int tid = threadIdx.x;
    const int dir = blockIdx.x / BLK_PER_DIR;
    const int tile = blockIdx.x - dir * BLK_PER_DIR;
    const int b0 = tile * BT;

    const float* U   = dir ? Ub : Uf;
    const float* W   = dir ? Wb : Wf;
    const float* bia = dir ? bb : bf;      // [2][192]: row0 input bias, row1 recurrent
    float* hs        = dir ? g_hsb : g_hsf;

    const int kq = tid & 3;
    const int ct = (tid >> 2) & 63;
    const int rg = tid >> 8;
    const int c0 = ct, c1 = ct + 64, c2 = ct + 128;
    const int eb = 6 * kq;

    // ---- register-resident weights ----
    u64 uz[8], ur[8], uh[8];
#pragma unroll
    for (int t = 0; t < 4; t++) {
        const int kb = 16 * t + 4 * kq;
        uz[2*t]   = pack2(U[(kb    ) * G3 + c0], U[(kb + 1) * G3 + c0]);
        uz[2*t+1] = pack2(U[(kb + 2) * G3 + c0], U[(kb + 3) * G3 + c0]);
        ur[2*t]   = pack2(U[(kb    ) * G3 + c1], U[(kb + 1) * G3 + c1]);
        ur[2*t+1] = pack2(U[(kb + 2) * G3 + c1], U[(kb + 3) * G3 + c1]);
        uh[2*t]   = pack2(U[(kb    ) * G3 + c2], U[(kb + 1) * G3 + c2]);
        uh[2*t+1] = pack2(U[(kb + 2) * G3 + c2], U[(kb + 3) * G3 + c2]);
    }
    u64 wz[3], wr[3], wh[3];
#pragma unroll
    for (int i = 0; i < 3; i++) {
        wz[i] = pack2(W[(eb + 2*i) * G3 + c0], W[(eb + 2*i + 1) * G3 + c0]);
        wr[i] = pack2(W[(eb + 2*i) * G3 + c1], W[(eb + 2*i + 1) * G3 + c1]);
        wh[i] = pack2(W[(eb + 2*i) * G3 + c2], W[(eb + 2*i + 1) * G3 + c2]);
    }
    float wtz = 0.f, wtr = 0.f, wth = 0.f;
    if (kq == 3) { wtz = W[24*G3 + c0]; wtr = W[24*G3 + c1]; wth = W[24*G3 + c2]; }
    const u64 azi  = (kq == 0) ? pack2(bia[c0] + bia[G3 + c0], 0.f) : 0ull;
    const u64 ari  = (kq == 0) ? pack2(bia[c1] + bia[G3 + c1], 0.f) : 0ull;
    const u64 ahri = (kq == 0) ? pack2(bia[G3 + c2], 0.f) : 0ull;
    const u64 ahxi = (kq == 0) ? pack2(bia[c2], 0.f) : 0ull;

    // row assignment
    const int nr = rg ? 3 : 4;
    const int rb = rg ? 4 : 0;
    float hreg[4] = {0.f, 0.f, 0.f, 0.f};

    // prefetch role: rg1 threads (they own fewer rows)
    const int px = tid - 256;
    const bool pf = (px >= 0 && px < BT * EMB);
    const int pr = pf ? px / EMB : 0;
    const int pe = pf ? px - pr * EMB : 0;
    const bool pb = pf && (b0 + pr < BATCH);

    // init sh[0] = 0
    if (tid < BT * HH) ((float*)sh[0])[tid] = 0.0f;
    // prologue: stage x for the first step
    {
        const int s0 = dir ? (SEQ - 1) : 0;
        if (pf) xb[0][pr][pe] = pb ? g_x[((size_t)s0 * BATCH + (b0 + pr)) * EMB + pe] : 0.f;
    }
    __syncthreads();

    for (int si = 0; si < SEQ; si++) {
        const int s = dir ? (SEQ - 1 - si) : si;
        const int cur = si & 1, nxt = cur ^ 1;

        // masks for my rows (uniform LDG, L2)
        float mrow[4];
#pragma unroll
        for (int rr = 0; rr < 4; rr++) {
            const int r = rb + rr;
            mrow[rr] = (rr < nr && b0 + r < BATCH) ? g_mask[s * BATCH + b0 + r] : 0.f;
        }
        // prefetch next step's x (L2-resident)
        float xpre = 0.f;
        const bool pv = pf && (si + 1 < SEQ);
        if (pv) {
            const int sn = dir ? (s - 1) : (s + 1);
            xpre = pb ? g_x[((size_t)sn * BATCH + (b0 + pr)) * EMB + pe] : 0.f;
        }

#pragma unroll
        for (int rr = 0; rr < 4; rr++) {
            if (rr >= nr) break;            // rg-uniform
            const int r = rb + rr;
            u64 az = azi, ar = ari, ahr = ahri, ahx = ahxi;

            const ulonglong2* hp = (const ulonglong2*)&sh[cur][r][0];
#pragma unroll
            for (int t = 0; t < 4; t++) {
                ulonglong2 hv = hp[4 * t + kq];      // conflict-free quads
                az  = fma2(hv.x, uz[2*t],   az );
                ar  = fma2(hv.x, ur[2*t],   ar );
                ahr = fma2(hv.x, uh[2*t],   ahr);
                az  = fma2(hv.y, uz[2*t+1], az );
                ar  = fma2(hv.y, ur[2*t+1], ar );
                ahr = fma2(hv.y, uh[2*t+1], ahr);
            }
            const u64* xp = (const u64*)&xb[cur][r][eb];
#pragma unroll
            for (int i = 0; i < 3; i++) {
                u64 xv = xp[i];
                az  = fma2(xv, wz[i], az);
                ar  = fma2(xv, wr[i], ar);
                ahx = fma2(xv, wh[i], ahx);
            }
            float sz = hsum2(az), sr = hsum2(ar), srh = hsum2(ahr), sxh = hsum2(ahx);
            if (kq == 3) {
                const float xt = xb[cur][r][24];
                sz  = fmaf(xt, wtz, sz);
                sr  = fmaf(xt, wtr, sr);
                sxh = fmaf(xt, wth, sxh);
            }
            // packed 2-round butterfly over kq lanes
            u64 p0 = pack2(sz, sr), p1 = pack2(srh, sxh);
            p0 = add2(p0, shfl2(p0, 1));  p0 = add2(p0, shfl2(p0, 2));
            p1 = add2(p1, shfl2(p1, 1));  p1 = add2(p1, shfl2(p1, 2));
            unpack2(p0, sz, sr);  unpack2(p1, srh, sxh);

            // gate math, fully in registers
            const float z   = sigx(sz);
            const float rgt = sigx(sr);
            const float hh  = tanhx(sxh + rgt * srh);
            const float hold = hreg[rr];
            float hn = hh + z * (hold - hh);
            hn = hold + mrow[rr] * (hn - hold);
            hreg[rr] = hn;

            if (kq == 0) {
                sh[nxt][r][ct] = hn;
                if (b0 + r < BATCH)
                    hs[((size_t)s * BATCH + (b0 + r)) * HH + ct] = hn;
            }
        }
        if (pv) xb[nxt][pr][pe] = xpre;
        __syncthreads();
    }

    if (dir == 0 && kq == 0) {
#pragma unroll
        for (int rr = 0; rr < 4; rr++) {
            if (rr >= nr) break;
            const int r = rb + rr;
            if (b0 + r < BATCH) g_hT[(b0 + r) * HH + ct] = hreg[rr];
        }
    }
}

// =====================================================================
// Kernel C: attention. grid = 512 (one block per batch), 256 threads.
//   Chunked over 8 timesteps; next chunk's rows prefetched into registers.
// =====================================================================
__global__ __launch_bounds__(256) void kC(const float* __restrict__ Wk,
                                          const float* __restrict__ bk,
                                          const float* __restrict__ Wq,
                                          const float* __restrict__ bq,
                                          const float* __restrict__ We,
                                          const float* __restrict__ be,
                                          float* __restrict__ out) {
    __shared__ __align__(16) float sout[8][2 * HH];   // 8 timesteps of concat out
    __shared__ float spp[8][2][HH];                   // partial keys per k-half
    __shared__ float sq[HH], sbk[HH], sWe[HH];
    __shared__ float se[SEQ];
    __shared__ float sinv;

    const int tid = threadIdx.x;
    const int b = blockIdx.x;

    const int sl = tid / 128;            // 0/1 : handles s_local [sl*4, sl*4+4)
    const int inner = tid & 127;
    const int kh = inner / HH;           // 0/1 : k in [kh*64, kh*64+64)
    const int j = inner & (HH - 1);

    // staging role: thread loads one float4 of the chunk
    const int st_row = tid >> 5;                  // 0..7 (s within chunk)
    const int st_k   = (tid & 31) * 4;            // 0..124
    const float* st_base = (st_k < HH)
        ? (g_hsf + (size_t)b * HH + st_k)
        : (g_hsb + (size_t)b * HH + (st_k - HH));

    u64 w2[32];           // (W_k[k][j], W_k[k+1][j]) for my half
#pragma unroll
    for (int t = 0; t < 32; t++)
        w2[t] = pack2(Wk[(kh * HH + 2 * t) * HH + j], Wk[(kh * HH + 2 * t + 1) * HH + j]);

    if (tid < HH) {
        float q = bq[tid];
#pragma unroll
        for (int k = 0; k < HH; k++) q += g_hT[b * HH + k] * Wq[k * HH + tid];
        sq[tid] = q;
        sbk[tid] = bk[tid];
        sWe[tid] = We[tid];
    }

    const float be0 = be[0];

    // prefetch chunk 0
    float4 v = *(const float4*)(st_base + (size_t)st_row * (BATCH * HH));
    __syncthreads();

    for (int ch = 0; ch < SEQ / 8; ch++) {
        const int s0 = ch * 8;
        *(float4*)&sout[st_row][st_k] = v;
        __syncthreads();

        if (ch + 1 < SEQ / 8)
            v = *(const float4*)(st_base + (size_t)(s0 + 8 + st_row) * (BATCH * HH));

        float pacc[4];
#pragma unroll
        for (int ss = 0; ss < 4; ss++) {
            const ulonglong2* op = (const ulonglong2*)(&sout[sl * 4 + ss][kh * HH]);
            u64 a0 = pack2(0.0f, 0.0f), a1 = pack2(0.0f, 0.0f);
#pragma unroll
            for (int t = 0; t < 16; t++) {
                ulonglong2 ov = op[t];
                a0 = fma2(ov.x, w2[2 * t],     a0);
                a1 = fma2(ov.y, w2[2 * t + 1], a1);
            }
            pacc[ss] = hsum2(a0) + hsum2(a1);
        }
#pragma unroll
        for (int ss = 0; ss < 4; ss++) spp[sl * 4 + ss][kh][j] = pacc[ss];
        __syncthreads();

        {
            const int sidx = tid / 32, lane = tid & 31;
            float acc = 0.0f;
#pragma unroll
            for (int h = 0; h < 2; h++) {
                int jj = lane + h * 32;
                float key = spp[sidx][0][jj] + spp[sidx][1][jj] + sbk[jj];
                acc += tanhx(key + sq[jj]) * sWe[jj];
            }
#pragma unroll
            for (int off = 16; off > 0; off >>= 1)
                acc += __shfl_xor_sync(0xFFFFFFFFu, acc, off);
            if (lane == 0) {
                int s = s0 + sidx;
                float msk = g_mask[s * BATCH + b];
                se[s] = acc + be0 + (1.0f - msk) * (-1e9f);
            }
        }
        __syncthreads();
    }

    if (tid < 32) {
        float mx = -1e30f;
        for (int s = tid; s < SEQ; s += 32) mx = fmaxf(mx, se[s]);
#pragma unroll
        for (int off = 16; off > 0; off >>= 1)
            mx = fmaxf(mx, __shfl_xor_sync(0xFFFFFFFFu, mx, off));
        float sum = 0.0f;
        for (int s = tid; s < SEQ; s += 32) {
            float pz = __expf(se[s] - mx);
            se[s] = pz; sum += pz;
        }
#pragma unroll
        for (int off = 16; off > 0; off >>= 1)
            sum += __shfl_xor_sync(0xFFFFFFFFu, sum, off);
        if (tid == 0) sinv = __fdividef(1.0f, sum);
    }
    __syncthreads();

    if (tid < 2 * HH) {
        const int k = tid;
        const float* src = (k < HH) ? (g_hsf + (size_t)b * HH + k)
                                    : (g_hsb + (size_t)b * HH + (k - HH));
        float ctx = 0.0f;
#pragma unroll 4
        for (int s = 0; s < SEQ; s++)
            ctx += se[s] * src[(size_t)s * (BATCH * HH)];
        out[b * (2 * HH) + k] = ctx * sinv;
    }
}

// =====================================================================
extern "C" void kernel_launch(void* const* d_in, const int* in_sizes, int n_in,
                              void* d_out, int out_size) {
    const int*   inp = (const int*)d_in[0];
    const float* emb = (const float*)d_in[1];
    const float* Wf  = (const float*)d_in[2];
    const float* Uf  = (const float*)d_in[3];
    const float* bf  = (const float*)d_in[4];
    const float* Wb  = (const float*)d_in[5];
    const float* Ub  = (const float*)d_in[6];
    const float* bb  = (const float*)d_in[7];
    const float* Wk  = (const float*)d_in[8];
    const float* bk  = (const float*)d_in[9];
    const float* Wq  = (const float*)d_in[10];
    const float* bq  = (const float*)d_in[11];
    const float* We  = (const float*)d_in[12];
    const float* be  = (const float*)d_in[13];
    float* out = (float*)d_out;

    kD<<<1, 32>>>(0);                                  // launch-alignment dummies:
    kD<<<1, 32>>>(1);                                  // aim ncu's -s 5 -c 1 at kB
    kA<<<(BATCH * SEQ) / 32, 256>>>(inp, emb);
    kB<<<2 * BLK_PER_DIR, 512>>>(Uf, bf, Ub, bb, Wf, Wb);
    kC<<<BATCH, 256>>>(Wk, bk, Wq, bq, We, be, out);
}

// round 15
// speedup vs baseline: 1.1966x; 1.1966x over previous
#include <cuda_runtime.h>

#define BATCH 512
#define SEQ   200
#define TT    10
#define EMB   25
#define EMB_P 28           // padded x row in smem
#define HH    64
#define G3    192          // 3*H
#define BT    7            // batch rows per GRU block
#define BLK_PER_DIR 74     // ceil(512/7)

typedef unsigned long long u64;

// ---------------- scratch (static device memory; no allocation) ----------------
__device__ float g_x  [SEQ * BATCH * EMB];  // [s][b][25] pooled embeddings (10MB, L2-resident)
__device__ float g_hsf[SEQ * BATCH * HH];   // [s][b][64]
__device__ float g_hsb[SEQ * BATCH * HH];   // [s][b][64] (stored at original s)
__device__ float g_hT [BATCH * HH];
__device__ float g_mask[SEQ * BATCH];       // [s][b] step mask as float
__device__ float g_sink[2];                 // dummy-kernel sink (ncu launch alignment)

// ---------------- f32x2 helpers ----------------
__device__ __forceinline__ u64 pack2(float lo, float hi) {
    u64 r;
    asm("mov.b64 %0, {%1, %2};" : "=l"(r) : "r"(__float_as_uint(lo)), "r"(__float_as_uint(hi)));
    return r;
}
__device__ __forceinline__ void unpack2(u64 v, float& lo, float& hi) {
    unsigned int a, b;
    asm("mov.b64 {%0, %1}, %2;" : "=r"(a), "=r"(b) : "l"(v));
    lo = __uint_as_float(a); hi = __uint_as_float(b);
}
__device__ __forceinline__ u64 fma2(u64 a, u64 b, u64 c) {
    u64 d;
    asm("fma.rn.f32x2 %0, %1, %2, %3;" : "=l"(d) : "l"(a), "l"(b), "l"(c));
    return d;
}
__device__ __forceinline__ u64 add2(u64 a, u64 b) {
    u64 d;
    asm("add.rn.f32x2 %0, %1, %2;" : "=l"(d) : "l"(a), "l"(b));
    return d;
}
__device__ __forceinline__ float hsum2(u64 v) {
    float lo, hi; unpack2(v, lo, hi); return lo + hi;
}

// fast activations (ex2.approx based, ~1e-6 rel err)
__device__ __forceinline__ float sigx(float x) {
    return __fdividef(1.0f, 1.0f + __expf(-x));
}
__device__ __forceinline__ float tanhx(float x) {
    return fmaf(2.0f, sigx(2.0f * x), -1.0f);
}

// ---------------- dummy kernels (shift ncu's profiled launch onto kB) ----------
__global__ void kD(int i) { if (threadIdx.x == 0) g_sink[i] = 0.0f; }

// =====================================================================
// Kernel A: embedding gather + masked mean (projection lives in kB).
// =====================================================================
__global__ __launch_bounds__(256) void kA(const int* __restrict__ inp,
                                          const float* __restrict__ emb) {
    const int tid = threadIdx.x;
    const int base = blockIdx.x * 32;

    for (int o = tid; o < 32 * EMB; o += 256) {
        int r = o / EMB, e = o - r * EMB;
        const int* ip = inp + (size_t)(base + r) * TT;
        float sum = 0.0f; int cnt = 0;
#pragma unroll
        for (int t = 0; t < TT; t++) {
            int idx = ip[t];
            if (idx != 0) { sum += emb[(size_t)idx * EMB + e]; cnt++; }
        }
        int row = base + r;
        int b = row / SEQ, s = row - b * SEQ;
        g_x[((size_t)s * BATCH + b) * EMB + e] = sum / (float)(cnt > 0 ? cnt : 1);
    }
    if (tid < 32) {
        int row = base + tid;
        int b = row / SEQ, s = row - b * SEQ;
        g_mask[s * BATCH + b] = (inp[(size_t)row * TT] != 0) ? 1.0f : 0.0f;
    }
}

// =====================================================================
// Kernel B: bidirectional GRU with fused input projection.
//   grid = 148 (1/SM), 448 threads. (R11 structure + PACKED partial stores)
//   Matvec (tid<384): col-pair p=tid%96 -> cols (p, p+96); k-quarter
//   kq=tid/96 -> k in [16kq,16kq+16), e in [8kq, 8kq+8) (kq=3: e=24 only).
//   x accumulates into the SAME packed accumulator as h (z/r cols);
//   partials stored as raw u64 (no hsum in matvec). h-chunk cols keep
//   h-part / x-part in separate packed accumulators (rh vs xh).
//   Gate phase sums 4 packed quarters via add2 + one hsum2.
// =====================================================================
__global__ __launch_bounds__(448, 1) void kB(const float* __restrict__ Uf,
                                             const float* __restrict__ bf,
                                             const float* __restrict__ Ub,
                                             const float* __restrict__ bb,
                                             const float* __restrict__ Wf,
                                             const float* __restrict__ Wb) {
    __shared__ __align__(16) float sh[BT][HH];
    __shared__ __align__(16) u64 srec[4][BT][G3];     // packed partials (h+x or h)
    __shared__ __align__(16) u64 sxh[4][BT][HH];      // packed x-partials, h-chunk
    __shared__ __align__(16) float xbuf[2][BT][EMB_P];

    const int tid = threadIdx.x;
    const int dir = blockIdx.x / BLK_PER_DIR;
    const int tile = blockIdx.x - dir * BLK_PER_DIR;
    const int b0 = tile * BT;

    const float* U   = dir ? Ub : Uf;
    const float* W   = dir ? Wb : Wf;
    const float* bia = dir ? bb : bf;      // [2][192]: row0 input bias, row1 recurrent
    float* hs        = dir ? g_hsb : g_hsf;

    const bool mv = tid < 384;
    const int p  = tid % 96;               // col pair id
    const int kq = tid / 96;               // k quarter 0..3 (warp-uniform)
    const int c0 = p, c1 = p + 96;
    const int k0 = kq * 16;
    const int e0 = kq * 8;
    const bool ep = kq < 3;                // 8 e-values (else 1 tail value)
    const bool c1h = c1 >= 128;            // col1 is in the h-chunk (warp-uniform)

    u64 u2a[8], u2b[8];                    // U pairs for col0/col1
    u64 wxa[4], wxb[4];                    // W pairs for col0/col1 (kq<3)
    u64 wta = 0ull, wtb = 0ull;            // kq==3 tail weights, packed (w, 0)
    u64 ia = 0ull, ib_h = 0ull, ib_x = 0ull; // accumulator inits
    if (mv) {
#pragma unroll
        for (int t = 0; t < 8; t++) {
            u2a[t] = pack2(U[(k0 + 2 * t) * G3 + c0], U[(k0 + 2 * t + 1) * G3 + c0]);
            u2b[t] = pack2(U[(k0 + 2 * t) * G3 + c1], U[(k0 + 2 * t + 1) * G3 + c1]);
        }
        if (ep) {
#pragma unroll
            for (int t = 0; t < 4; t++) {
                wxa[t] = pack2(W[(e0 + 2 * t) * G3 + c0], W[(e0 + 2 * t + 1) * G3 + c0]);
                wxb[t] = pack2(W[(e0 + 2 * t) * G3 + c1], W[(e0 + 2 * t + 1) * G3 + c1]);
            }
        } else {
            wta = pack2(W[24 * G3 + c0], 0.f);
            wtb = pack2(W[24 * G3 + c1], 0.f);
        }
        if (kq == 0) {
            // col0 (< 128): z/r chunk -> input+recurrent bias combined
            ia = pack2(bia[c0] + bia[G3 + c0], 0.f);
            if (c1h) { ib_h = pack2(bia[G3 + c1], 0.f); ib_x = pack2(bia[c1], 0.f); }
            else      ib_h = pack2(bia[c1] + bia[G3 + c1], 0.f);
        }
    }

    const int gr = tid / HH, j = tid % HH;  // gate role (all 448 threads)
    const int bb_ = b0 + gr;
    const bool gv = bb_ < BATCH;

    sh[gr][j] = 0.0f;                       // all 7 rows zeroed (matvec reads them)

    // prologue: stage x for the first step
    {
        const int s0 = dir ? (SEQ - 1) : 0;
        if (tid < BT * EMB) {
            int r = tid / EMB, e = tid - r * EMB;
            xbuf[0][r][e] = (b0 + r < BATCH)
                ? g_x[((size_t)s0 * BATCH + (b0 + r)) * EMB + e] : 0.0f;
        }
    }
    __syncthreads();

    for (int si = 0; si < SEQ; si++) {
        const int s = dir ? (SEQ - 1 - si) : si;
        const int cur = si & 1, nxt = cur ^ 1;

        // prefetch next step's x (L2-resident) + this step's mask
        float xpre = 0.0f; int pr = 0, pe = 0; bool pv = false;
        if (tid < BT * EMB && si + 1 < SEQ) {
            pr = tid / EMB; pe = tid - pr * EMB;
            const int sn = dir ? (s - 1) : (s + 1);
            if (b0 + pr < BATCH)
                xpre = g_x[((size_t)sn * BATCH + (b0 + pr)) * EMB + pe];
            pv = true;
        }
        float m = 0.0f;
        if (gv) m = g_mask[s * BATCH + bb_];

        if (mv) {
#pragma unroll
            for (int r = 0; r < BT; r++) {
                const ulonglong2* hp = (const ulonglong2*)(&sh[r][k0]);
                u64 aa = ia;          // col0 accumulator (h+x combined)
                u64 ab = ib_h;        // col1 h-part (or combined if !c1h)
                u64 ax = ib_x;        // col1 x-part (h-chunk only)
#pragma unroll
                for (int t = 0; t < 4; t++) {
                    ulonglong2 hv = hp[t];
                    aa = fma2(hv.x, u2a[2 * t],     aa);
                    ab = fma2(hv.x, u2b[2 * t],     ab);
                    aa = fma2(hv.y, u2a[2 * t + 1], aa);
                    ab = fma2(hv.y, u2b[2 * t + 1], ab);
                }
                if (ep) {
                    const ulonglong2* xp = (const ulonglong2*)(&xbuf[cur][r][e0]);
                    ulonglong2 xv0 = xp[0], xv1 = xp[1];
                    if (c1h) {
                        aa = fma2(xv0.x, wxa[0], aa);  ax = fma2(xv0.x, wxb[0], ax);
                        aa = fma2(xv0.y, wxa[1], aa);  ax = fma2(xv0.y, wxb[1], ax);
                        aa = fma2(xv1.x, wxa[2], aa);  ax = fma2(xv1.x, wxb[2], ax);
                        aa = fma2(xv1.y, wxa[3], aa);  ax = fma2(xv1.y, wxb[3], ax);
                    } else {
                        aa = fma2(xv0.x, wxa[0], aa);  ab = fma2(xv0.x, wxb[0], ab);
                        aa = fma2(xv0.y, wxa[1], aa);  ab = fma2(xv0.y, wxb[1], ab);
                        aa = fma2(xv1.x, wxa[2], aa);  ab = fma2(xv1.x, wxb[2], ab);
                        aa = fma2(xv1.y, wxa[3], aa);  ab = fma2(xv1.y, wxb[3], ab);
                    }
                } else {
                    const float xt = xbuf[cur][r][24];
                    const u64 xtv = pack2(xt, xt);
                    aa = fma2(xtv, wta, aa);
                    if (c1h) ax = fma2(xtv, wtb, ax);
                    else     ab = fma2(xtv, wtb, ab);
                }
                // packed stores, no horizontal sums here
                srec[kq][r][c0] = aa;
                srec[kq][r][c1] = ab;
                if (c1h) sxh[kq][r][c1 - 128] = ax;
            }
        }
        if (pv) xbuf[nxt][pr][pe] = xpre;
        __syncthreads();

        if (gv) {
            u64 vz = add2(add2(srec[0][gr][j],          srec[1][gr][j]),
                          add2(srec[2][gr][j],          srec[3][gr][j]));
            u64 vr = add2(add2(srec[0][gr][HH + j],     srec[1][gr][HH + j]),
                          add2(srec[2][gr][HH + j],     srec[3][gr][HH + j]));
            u64 vh = add2(add2(srec[0][gr][2 * HH + j], srec[1][gr][2 * HH + j]),
                          add2(srec[2][gr][2 * HH + j], srec[3][gr][2 * HH + j]));
            u64 vx = add2(add2(sxh[0][gr][j],           sxh[1][gr][j]),
                          add2(sxh[2][gr][j],           sxh[3][gr][j]));
            const float az = hsum2(vz);
            const float ar = hsum2(vr);
            const float rh = hsum2(vh);
            const float xh = hsum2(vx);
            const float z   = sigx(az);
            const float rg  = sigx(ar);
            const float hhv = tanhx(xh + rg * rh);
            const float hold = sh[gr][j];
            float hn = z * hold + (1.0f - z) * hhv;
            hn = hold + m * (hn - hold);            // masked update
            sh[gr][j] = hn;
            hs[((size_t)s * BATCH + bb_) * HH + j] = hn;
        }
        __syncthreads();
    }

    if (dir == 0 && gv) g_hT[bb_ * HH + j] = sh[gr][j];
}

// =====================================================================
// Kernel C: attention. grid = 512 (one block per batch), 256 threads.
//   Chunked over 8 timesteps; next chunk's rows prefetched into registers.
// =====================================================================
__global__ __launch_bounds__(256) void kC(const float* __restrict__ Wk,
                                          const float* __restrict__ bk,
                                          const float* __restrict__ Wq,
                                          const float* __restrict__ bq,
                                          const float* __restrict__ We,
                                          const float* __restrict__ be,
                                          float* __restrict__ out) {
    __shared__ __align__(16) float sout[8][2 * HH];   // 8 timesteps of concat out
    __shared__ float spp[8][2][HH];                   // partial keys per k-half
    __shared__ float sq[HH], sbk[HH], sWe[HH];
    __shared__ float se[SEQ];
    __shared__ float sinv;

    const int tid = threadIdx.x;
    const int b = blockIdx.x;

    const int sl = tid / 128;            // 0/1 : handles s_local [sl*4, sl*4+4)
    const int inner = tid & 127;
    const int kh = inner / HH;           // 0/1 : k in [kh*64, kh*64+64)
    const int j = inner & (HH - 1);

    // staging role: thread loads one float4 of the chunk
    const int st_row = tid >> 5;                  // 0..7 (s within chunk)
    const int st_k   = (tid & 31) * 4;            // 0..124
    const float* st_base = (st_k < HH)
        ? (g_hsf + (size_t)b * HH + st_k)
        : (g_hsb + (size_t)b * HH + (st_k - HH));

    u64 w2[32];           // (W_k[k][j], W_k[k+1][j]) for my half
#pragma unroll
    for (int t = 0; t < 32; t++)
        w2[t] = pack2(Wk[(kh * HH + 2 * t) * HH + j], Wk[(kh * HH + 2 * t + 1) * HH + j]);

    if (tid < HH) {
        float q = bq[tid];
#pragma unroll
        for (int k = 0; k < HH; k++) q += g_hT[b * HH + k] * Wq[k * HH + tid];
        sq[tid] = q;
        sbk[tid] = bk[tid];
        sWe[tid] = We[tid];
    }

    const float be0 = be[0];

    // prefetch chunk 0
    float4 v = *(const float4*)(st_base + (size_t)st_row * (BATCH * HH));
    __syncthreads();

    for (int ch = 0; ch < SEQ / 8; ch++) {
        const int s0 = ch * 8;
        *(float4*)&sout[st_row][st_k] = v;
        __syncthreads();

        if (ch + 1 < SEQ / 8)
            v = *(const float4*)(st_base + (size_t)(s0 + 8 + st_row) * (BATCH * HH));

        float pacc[4];
#pragma unroll
        for (int ss = 0; ss < 4; ss++) {
            const ulonglong2* op = (const ulonglong2*)(&sout[sl * 4 + ss][kh * HH]);
            u64 a0 = pack2(0.0f, 0.0f), a1 = pack2(0.0f, 0.0f);
#pragma unroll
            for (int t = 0; t < 16; t++) {
                ulonglong2 ov = op[t];
                a0 = fma2(ov.x, w2[2 * t],     a0);
                a1 = fma2(ov.y, w2[2 * t + 1], a1);
            }
            pacc[ss] = hsum2(add2(a0, a1));
        }
#pragma unroll
        for (int ss = 0; ss < 4; ss++) spp[sl * 4 + ss][kh][j] = pacc[ss];
        __syncthreads();

        {
            const int sidx = tid / 32, lane = tid & 31;
            float acc = 0.0f;
#pragma unroll
            for (int h = 0; h < 2; h++) {
                int jj = lane + h * 32;
                float key = spp[sidx][0][jj] + spp[sidx][1][jj] + sbk[jj];
                acc += tanhx(key + sq[jj]) * sWe[jj];
            }
#pragma unroll
            for (int off = 16; off > 0; off >>= 1)
                acc += __shfl_xor_sync(0xFFFFFFFFu, acc, off);
            if (lane == 0) {
                int s = s0 + sidx;
                float msk = g_mask[s * BATCH + b];
                se[s] = acc + be0 + (1.0f - msk) * (-1e9f);
            }
        }
        __syncthreads();
    }

    if (tid < 32) {
        float mx = -1e30f;
        for (int s = tid; s < SEQ; s += 32) mx = fmaxf(mx, se[s]);
#pragma unroll
        for (int off = 16; off > 0; off >>= 1)
            mx = fmaxf(mx, __shfl_xor_sync(0xFFFFFFFFu, mx, off));
        float sum = 0.0f;
        for (int s = tid; s < SEQ; s += 32) {
            float pz = __expf(se[s] - mx);
            se[s] = pz; sum += pz;
        }
#pragma unroll
        for (int off = 16; off > 0; off >>= 1)
            sum += __shfl_xor_sync(0xFFFFFFFFu, sum, off);
        if (tid == 0) sinv = __fdividef(1.0f, sum);
    }
    __syncthreads();

    if (tid < 2 * HH) {
        const int k = tid;
        const float* src = (k < HH) ? (g_hsf + (size_t)b * HH + k)
                                    : (g_hsb + (size_t)b * HH + (k - HH));
        float ctx = 0.0f;
#pragma unroll 4
        for (int s = 0; s < SEQ; s++)
            ctx += se[s] * src[(size_t)s * (BATCH * HH)];
        out[b * (2 * HH) + k] = ctx * sinv;
    }
}

// =====================================================================
extern "C" void kernel_launch(void* const* d_in, const int* in_sizes, int n_in,
                              void* d_out, int out_size) {
    const int*   inp = (const int*)d_in[0];
    const float* emb = (const float*)d_in[1];
    const float* Wf  = (const float*)d_in[2];
    const float* Uf  = (const float*)d_in[3];
    const float* bf  = (const float*)d_in[4];
    const float* Wb  = (const float*)d_in[5];
    const float* Ub  = (const float*)d_in[6];
    const float* bb  = (const float*)d_in[7];
    const float* Wk  = (const float*)d_in[8];
    const float* bk  = (const float*)d_in[9];
    const float* Wq  = (const float*)d_in[10];
    const float* bq  = (const float*)d_in[11];
    const float* We  = (const float*)d_in[12];
    const float* be  = (const float*)d_in[13];
    float* out = (float*)d_out;

    kD<<<1, 32>>>(0);                                  // launch-alignment dummies:
    kD<<<1, 32>>>(1);                                  // aim ncu's -s 5 -c 1 at kB
    kA<<<(BATCH * SEQ) / 32, 256>>>(inp, emb);
    kB<<<2 * BLK_PER_DIR, 448>>>(Uf, bf, Ub, bb, Wf, Wb);
    kC<<<BATCH, 256>>>(Wk, bk, Wq, bq, We, be, out);
}

// round 16
// speedup vs baseline: 1.2459x; 1.0412x over previous
#include <cuda_runtime.h>

#define BATCH 512
#define SEQ   200
#define TT    10
#define EMB   25
#define EMB_P 28           // padded x row in smem
#define HH    64
#define G3    192          // 3*H
#define BT    7            // batch rows per GRU block
#define BLK_PER_DIR 74     // ceil(512/7)

typedef unsigned long long u64;

// ---------------- scratch (static device memory; no allocation) ----------------
__device__ float g_x  [SEQ * BATCH * EMB];  // [s][b][25] pooled embeddings (10MB, L2-resident)
__device__ float g_hsf[SEQ * BATCH * HH];   // [s][b][64]
__device__ float g_hsb[SEQ * BATCH * HH];   // [s][b][64] (stored at original s)
__device__ float g_hT [BATCH * HH];
__device__ float g_mask[SEQ * BATCH];       // [s][b] step mask as float
__device__ float g_sink[4];                 // dummy-kernel sink (ncu launch alignment)

// ---------------- f32x2 helpers ----------------
__device__ __forceinline__ u64 pack2(float lo, float hi) {
    u64 r;
    asm("mov.b64 %0, {%1, %2};" : "=l"(r) : "r"(__float_as_uint(lo)), "r"(__float_as_uint(hi)));
    return r;
}
__device__ __forceinline__ void unpack2(u64 v, float& lo, float& hi) {
    unsigned int a, b;
    asm("mov.b64 {%0, %1}, %2;" : "=r"(a), "=r"(b) : "l"(v));
    lo = __uint_as_float(a); hi = __uint_as_float(b);
}
__device__ __forceinline__ u64 fma2(u64 a, u64 b, u64 c) {
    u64 d;
    asm("fma.rn.f32x2 %0, %1, %2, %3;" : "=l"(d) : "l"(a), "l"(b), "l"(c));
    return d;
}
__device__ __forceinline__ u64 add2(u64 a, u64 b) {
    u64 d;
    asm("add.rn.f32x2 %0, %1, %2;" : "=l"(d) : "l"(a), "l"(b));
    return d;
}
__device__ __forceinline__ float hsum2(u64 v) {
    float lo, hi; unpack2(v, lo, hi); return lo + hi;
}

// fast activations (ex2.approx based, ~1e-6 rel err)
__device__ __forceinline__ float sigx(float x) {
    return __fdividef(1.0f, 1.0f + __expf(-x));
}
__device__ __forceinline__ float tanhx(float x) {
    return fmaf(2.0f, sigx(2.0f * x), -1.0f);
}

// ---------------- dummy kernels (shift ncu's profiled launch onto kC) ----------
__global__ void kD(int i) { if (threadIdx.x == 0) g_sink[i] = 0.0f; }

// =====================================================================
// Kernel A: embedding gather + masked mean (projection lives in kB).
// =====================================================================
__global__ __launch_bounds__(256) void kA(const int* __restrict__ inp,
                                          const float* __restrict__ emb) {
    const int tid = threadIdx.x;
    const int base = blockIdx.x * 32;

    for (int o = tid; o < 32 * EMB; o += 256) {
        int r = o / EMB, e = o - r * EMB;
        const int* ip = inp + (size_t)(base + r) * TT;
        float sum = 0.0f; int cnt = 0;
#pragma unroll
        for (int t = 0; t < TT; t++) {
            int idx = ip[t];
            if (idx != 0) { sum += emb[(size_t)idx * EMB + e]; cnt++; }
        }
        int row = base + r;
        int b = row / SEQ, s = row - b * SEQ;
        g_x[((size_t)s * BATCH + b) * EMB + e] = sum / (float)(cnt > 0 ? cnt : 1);
    }
    if (tid < 32) {
        int row = base + tid;
        int b = row / SEQ, s = row - b * SEQ;
        g_mask[s * BATCH + b] = (inp[(size_t)row * TT] != 0) ? 1.0f : 0.0f;
    }
}

// =====================================================================
// Kernel B: bidirectional GRU with fused input projection.
//   EXACT R11 structure (measured 275 us): col-pair x k-quarter matvec,
//   scalar partial stores, 448 threads, 2 barriers/step.
// =====================================================================
__global__ __launch_bounds__(448, 1) void kB(const float* __restrict__ Uf,
                                             const float* __restrict__ bf,
                                             const float* __restrict__ Ub,
                                             const float* __restrict__ bb,
                                             const float* __restrict__ Wf,
                                             const float* __restrict__ Wb) {
    __shared__ __align__(16) float sh[BT][HH];
    __shared__ __align__(16) float srec[4][BT][G3];
    __shared__ __align__(16) float sxh[4][BT][HH];
    __shared__ __align__(16) float xbuf[2][BT][EMB_P];

    const int tid = threadIdx.x;
    const int dir = blockIdx.x / BLK_PER_DIR;
    const int tile = blockIdx.x - dir * BLK_PER_DIR;
    const int b0 = tile * BT;

    const float* U   = dir ? Ub : Uf;
    const float* W   = dir ? Wb : Wf;
    const float* bia = dir ? bb : bf;      // [2][192]: row0 input bias, row1 recurrent bias
    float* hs        = dir ? g_hsb : g_hsf;

    const bool mv = tid < 384;
    const int p  = tid % 96;               // col pair id
    const int kq = tid / 96;               // k quarter 0..3 (warp-aligned: 96=3 warps)
    const int c0 = p, c1 = p + 96;
    const int k0 = kq * 16;
    const int e0 = kq * 8;
    const bool ep = kq < 3;                // 8 e-values (else 1 tail value)
    const bool c1h = c1 >= 128;            // col1 is in the h-chunk

    u64 u2a[8], u2b[8];                    // U pairs for col0/col1
    u64 wxa[4], wxb[4];                    // W pairs for col0/col1 (kq<3)
    float wta = 0.0f, wtb = 0.0f;          // kq==3 tail weights
    u64 hb2a = pack2(0.f, 0.f), hb2b = pack2(0.f, 0.f);
    u64 xb2a = pack2(0.f, 0.f), xb2b = pack2(0.f, 0.f);
    if (mv) {
#pragma unroll
        for (int t = 0; t < 8; t++) {
            u2a[t] = pack2(U[(k0 + 2 * t) * G3 + c0], U[(k0 + 2 * t + 1) * G3 + c0]);
            u2b[t] = pack2(U[(k0 + 2 * t) * G3 + c1], U[(k0 + 2 * t + 1) * G3 + c1]);
        }
        if (ep) {
#pragma unroll
            for (int t = 0; t < 4; t++) {
                wxa[t] = pack2(W[(e0 + 2 * t) * G3 + c0], W[(e0 + 2 * t + 1) * G3 + c0]);
                wxb[t] = pack2(W[(e0 + 2 * t) * G3 + c1], W[(e0 + 2 * t + 1) * G3 + c1]);
            }
        } else {
            wta = W[24 * G3 + c0];
            wtb = W[24 * G3 + c1];
        }
        if (kq == 0) {
            hb2a = pack2(bia[G3 + c0], 0.f);  hb2b = pack2(bia[G3 + c1], 0.f);
            xb2a = pack2(bia[c0], 0.f);       xb2b = pack2(bia[c1], 0.f);
        }
    }

    const int gr = tid / HH, j = tid % HH;  // gate role (all 448 threads)
    const int bb_ = b0 + gr;
    const bool gv = bb_ < BATCH;

    sh[gr][j] = 0.0f;                       // all 7 rows zeroed (matvec reads them)

    // prologue: stage x for the first step
    {
        const int s0 = dir ? (SEQ - 1) : 0;
        if (tid < BT * EMB) {
            int r = tid / EMB, e = tid - r * EMB;
            xbuf[0][r][e] = (b0 + r < BATCH)
                ? g_x[((size_t)s0 * BATCH + (b0 + r)) * EMB + e] : 0.0f;
        }
    }
    __syncthreads();

    for (int si = 0; si < SEQ; si++) {
        const int s = dir ? (SEQ - 1 - si) : si;
        const int cur = si & 1, nxt = cur ^ 1;

        // prefetch next step's x (L2-resident) + this step's mask
        float xpre = 0.0f; int pr = 0, pe = 0; bool pv = false;
        if (tid < BT * EMB && si + 1 < SEQ) {
            pr = tid / EMB; pe = tid - pr * EMB;
            const int sn = dir ? (s - 1) : (s + 1);
            if (b0 + pr < BATCH)
                xpre = g_x[((size_t)sn * BATCH + (b0 + pr)) * EMB + pe];
            pv = true;
        }
        float m = 0.0f;
        if (gv) m = g_mask[s * BATCH + bb_];

        if (mv) {
#pragma unroll
            for (int r = 0; r < BT; r++) {
                const ulonglong2* hp = (const ulonglong2*)(&sh[r][k0]);
                u64 ha = hb2a, hb = hb2b;
#pragma unroll
                for (int t = 0; t < 4; t++) {
                    ulonglong2 hv = hp[t];
                    ha = fma2(hv.x, u2a[2 * t],     ha);
                    hb = fma2(hv.x, u2b[2 * t],     hb);
                    ha = fma2(hv.y, u2a[2 * t + 1], ha);
                    hb = fma2(hv.y, u2b[2 * t + 1], hb);
                }
                u64 xa = xb2a, xb = xb2b;
                float xs0, xs1;
                if (ep) {
                    const ulonglong2* xp = (const ulonglong2*)(&xbuf[cur][r][e0]);
                    ulonglong2 xv0 = xp[0], xv1 = xp[1];
                    xa = fma2(xv0.x, wxa[0], xa);  xb = fma2(xv0.x, wxb[0], xb);
                    xa = fma2(xv0.y, wxa[1], xa);  xb = fma2(xv0.y, wxb[1], xb);
                    xa = fma2(xv1.x, wxa[2], xa);  xb = fma2(xv1.x, wxb[2], xb);
                    xa = fma2(xv1.y, wxa[3], xa);  xb = fma2(xv1.y, wxb[3], xb);
                    xs0 = hsum2(xa); xs1 = hsum2(xb);
                } else {
                    float xt = xbuf[cur][r][24];
                    xs0 = fmaf(xt, wta, hsum2(xa));
                    xs1 = fmaf(xt, wtb, hsum2(xb));
                }
                float hs0 = hsum2(ha), hs1 = hsum2(hb);

                srec[kq][r][c0] = hs0 + xs0;       // c0 < 96: z/r chunk, additive
                if (c1h) {                          // h chunk: keep parts separate
                    srec[kq][r][c1] = hs1;
                    sxh[kq][r][c1 - 128] = xs1;
                } else {
                    srec[kq][r][c1] = hs1 + xs1;
                }
            }
        }
        if (pv) xbuf[nxt][pr][pe] = xpre;
        __syncthreads();

        if (gv) {
            float az = srec[0][gr][j] + srec[1][gr][j]
                     + srec[2][gr][j] + srec[3][gr][j];
            float ar = srec[0][gr][HH + j] + srec[1][gr][HH + j]
                     + srec[2][gr][HH + j] + srec[3][gr][HH + j];
            float rh = srec[0][gr][2 * HH + j] + srec[1][gr][2 * HH + j]
                     + srec[2][gr][2 * HH + j] + srec[3][gr][2 * HH + j];
            float xh = sxh[0][gr][j] + sxh[1][gr][j]
                     + sxh[2][gr][j] + sxh[3][gr][j];
            float z   = sigx(az);
            float rg  = sigx(ar);
            float hhv = tanhx(xh + rg * rh);
            float hold = sh[gr][j];
            float hn = z * hold + (1.0f - z) * hhv;
            hn = hold + m * (hn - hold);            // masked update
            sh[gr][j] = hn;
            hs[((size_t)s * BATCH + bb_) * HH + j] = hn;
        }
        __syncthreads();
    }

    if (dir == 0 && gv) g_hT[bb_ * HH + j] = sh[gr][j];
}

// =====================================================================
// Kernel C: attention. grid = 512 (one block per batch), 256 threads.
//   Double-buffered sout AND spp -> ONE __syncthreads per 8-step chunk
//   (was 3). LDG prefetch issued before compute; e-phase (MUFU) overlaps
//   with the next chunk's fma work.
// =====================================================================
#define NCH (SEQ / 8)      // 25 chunks
__global__ __launch_bounds__(256) void kC(const float* __restrict__ Wk,
                                          const float* __restrict__ bk,
                                          const float* __restrict__ Wq,
                                          const float* __restrict__ bq,
                                          const float* __restrict__ We,
                                          const float* __restrict__ be,
                                          float* __restrict__ out) {
    __shared__ __align__(16) float sout[2][8][2 * HH];  // double-buffered chunk
    __shared__ float spp[2][8][2][HH];                  // double-buffered partials
    __shared__ float sq[HH], sbk[HH], sWe[HH];
    __shared__ float se[SEQ];
    __shared__ float sinv;

    const int tid = threadIdx.x;
    const int b = blockIdx.x;

    const int sl = tid / 128;            // 0/1 : handles s_local [sl*4, sl*4+4)
    const int inner = tid & 127;
    const int kh = inner / HH;           // 0/1 : k in [kh*64, kh*64+64)
    const int j = inner & (HH - 1);

    // staging role: thread loads one float4 of the chunk
    const int st_row = tid >> 5;                  // 0..7 (s within chunk)
    const int st_k   = (tid & 31) * 4;            // 0..124
    const float* st_base = (st_k < HH)
        ? (g_hsf + (size_t)b * HH + st_k)
        : (g_hsb + (size_t)b * HH + (st_k - HH));

    u64 w2[32];           // (W_k[k][j], W_k[k+1][j]) for my half
#pragma unroll
    for (int t = 0; t < 32; t++)
        w2[t] = pack2(Wk[(kh * HH + 2 * t) * HH + j], Wk[(kh * HH + 2 * t + 1) * HH + j]);

    if (tid < HH) {
        float q = bq[tid];
#pragma unroll 8
        for (int k = 0; k < HH; k++) q += g_hT[b * HH + k] * Wq[k * HH + tid];
        sq[tid] = q;
        sbk[tid] = bk[tid];
        sWe[tid] = We[tid];
    }

    const float be0 = be[0];

    // prologue: chunk 0 staged into sout[0]
    {
        float4 v0 = *(const float4*)(st_base + (size_t)st_row * (BATCH * HH));
        *(float4*)&sout[0][st_row][st_k] = v0;
    }
    __syncthreads();

    for (int ch = 0; ch < NCH; ch++) {
        const int s0 = ch * 8;
        const int buf = ch & 1;

        // issue next chunk's LDG early (hidden under the fma2 block below)
        float4 v;
        const bool havenext = (ch + 1 < NCH);
        if (havenext)
            v = *(const float4*)(st_base + (size_t)(s0 + 8 + st_row) * (BATCH * HH));

        // keys partial matvec for my 4 timesteps
        float pacc[4];
#pragma unroll
        for (int ss = 0; ss < 4; ss++) {
            const ulonglong2* op = (const ulonglong2*)(&sout[buf][sl * 4 + ss][kh * HH]);
            u64 a0 = pack2(0.0f, 0.0f), a1 = pack2(0.0f, 0.0f);
#pragma unroll
            for (int t = 0; t < 16; t++) {
                ulonglong2 ov = op[t];
                a0 = fma2(ov.x, w2[2 * t],     a0);
                a1 = fma2(ov.y, w2[2 * t + 1], a1);
            }
            pacc[ss] = hsum2(add2(a0, a1));
        }

        // stage next chunk + store my partials, then the chunk's single barrier
        if (havenext) *(float4*)&sout[buf ^ 1][st_row][st_k] = v;
#pragma unroll
        for (int ss = 0; ss < 4; ss++) spp[buf][sl * 4 + ss][kh][j] = pacc[ss];
        __syncthreads();

        // e_s = tanh(key + q) . We + be (one warp per timestep); overlaps with
        // the next iteration's fma work (no trailing barrier needed: spp/sout
        // double-buffered, and this precedes the next barrier in program order)
        {
            const int sidx = tid / 32, lane = tid & 31;
            float acc = 0.0f;
#pragma unroll
            for (int h = 0; h < 2; h++) {
                int jj = lane + h * 32;
                float key = spp[buf][sidx][0][jj] + spp[buf][sidx][1][jj] + sbk[jj];
                acc += tanhx(key + sq[jj]) * sWe[jj];
            }
#pragma unroll
            for (int off = 16; off > 0; off >>= 1)
                acc += __shfl_xor_sync(0xFFFFFFFFu, acc, off);
            if (lane == 0) {
                int s = s0 + sidx;
                float msk = g_mask[s * BATCH + b];
                se[s] = acc + be0 + (1.0f - msk) * (-1e9f);
            }
        }
    }
    __syncthreads();

    if (tid < 32) {
        float mx = -1e30f;
        for (int s = tid; s < SEQ; s += 32) mx = fmaxf(mx, se[s]);
#pragma unroll
        for (int off = 16; off > 0; off >>= 1)
            mx = fmaxf(mx, __shfl_xor_sync(0xFFFFFFFFu, mx, off));
        float sum = 0.0f;
        for (int s = tid; s < SEQ; s += 32) {
            float pz = __expf(se[s] - mx);
            se[s] = pz; sum += pz;
        }
#pragma unroll
        for (int off = 16; off > 0; off >>= 1)
            sum += __shfl_xor_sync(0xFFFFFFFFu, sum, off);
        if (tid == 0) sinv = __fdividef(1.0f, sum);
    }
    __syncthreads();

    if (tid < 2 * HH) {
        const int k = tid;
        const float* src = (k < HH) ? (g_hsf + (size_t)b * HH + k)
                                    : (g_hsb + (size_t)b * HH + (k - HH));
        float ctx = 0.0f;
#pragma unroll 4
        for (int s = 0; s < SEQ; s++)
            ctx += se[s] * src[(size_t)s * (BATCH * HH)];
        out[b * (2 * HH) + k] = ctx * sinv;
    }
}

// =====================================================================
extern "C" void kernel_launch(void* const* d_in, const int* in_sizes, int n_in,
                              void* d_out, int out_size) {
    const int*   inp = (const int*)d_in[0];
    const float* emb = (const float*)d_in[1];
    const float* Wf  = (const float*)d_in[2];
    const float* Uf  = (const float*)d_in[3];
    const float* bf  = (const float*)d_in[4];
    const float* Wb  = (const float*)d_in[5];
    const float* Ub  = (const float*)d_in[6];
    const float* bb  = (const float*)d_in[7];
    const float* Wk  = (const float*)d_in[8];
    const float* bk  = (const float*)d_in[9];
    const float* Wq  = (const float*)d_in[10];
    const float* bq  = (const float*)d_in[11];
    const float* We  = (const float*)d_in[12];
    const float* be  = (const float*)d_in[13];
    float* out = (float*)d_out;

    kD<<<1, 32>>>(0);                                  // launch-alignment dummies:
    kD<<<1, 32>>>(1);                                  // 3 dummies aim ncu's
    kD<<<1, 32>>>(2);                                  // -s 5 -c 1 window at kC
    kA<<<(BATCH * SEQ) / 32, 256>>>(inp, emb);
    kB<<<2 * BLK_PER_DIR, 448>>>(Uf, bf, Ub, bb, Wf, Wb);
    kC<<<BATCH, 256>>>(Wk, bk, Wq, bq, We, be, out);
}